// round 16
// baseline (speedup 1.0000x reference)
#include <cuda_runtime.h>
#include <cuda_bf16.h>
#include <cstdint>

#define B_  64
#define D_  128
#define LC  1024
#define LQ  256
#define FST 36       // fp32 smem row stride (144B: conflict-free STS.128 + ldmatrix)

// ---------------- scratch (static device arrays) ----------------
static __device__ float g_E [(size_t)B_*LC*LQ];     // exp(S + biases), tf32-rounded
static __device__ float g_Tt[(size_t)B_*2*D_*LQ];   // Tt partials: [b][split][d][m'], pre-scaled by qcinv
static __device__ float g_rp[(size_t)B_*2*LC];      // rowsum partials (per x-tile)
static __device__ float g_cp[(size_t)B_*8*LQ];      // colsum partials (per y-tile)

// ---------------- helpers ----------------
__device__ __forceinline__ uint32_t smem_u32(const void* p) {
    uint32_t a;
    asm("{ .reg .u64 t; cvta.to.shared.u64 t, %1; cvt.u32.u64 %0, t; }" : "=r"(a) : "l"(p));
    return a;
}

__device__ __forceinline__ float tf32r(float x) {
    uint32_t o; asm("cvt.rna.tf32.f32 %0, %1;" : "=r"(o) : "f"(x));
    return __uint_as_float(o);
}

#define LDSM_X4(r, a) \
    asm volatile("ldmatrix.sync.aligned.m8n8.x4.shared.b16 {%0,%1,%2,%3}, [%4];" \
        : "=r"((r)[0]), "=r"((r)[1]), "=r"((r)[2]), "=r"((r)[3]) : "r"(a))

#define MMA_TF32(c, a, b0, b1) \
    asm volatile("mma.sync.aligned.m16n8k8.row.col.f32.tf32.tf32.f32 " \
        "{%0,%1,%2,%3}, {%4,%5,%6,%7}, {%8,%9}, {%0,%1,%2,%3};" \
        : "+f"((c)[0]), "+f"((c)[1]), "+f"((c)[2]), "+f"((c)[3]) \
        : "r"((a)[0]), "r"((a)[1]), "r"((a)[2]), "r"((a)[3]), "r"(b0), "r"(b1))

template<bool CV>
__device__ __forceinline__ float4 cvt_sel(const float4& x) {
    if constexpr (!CV) return x;
    float4 t;
    t.x = tf32r(x.x); t.y = tf32r(x.y); t.z = tf32r(x.z); t.w = tf32r(x.w);
    return t;
}

// ---------------- shared MMA phase (A 128-row, B 128-col tiles in smem) ----------------
#define MMA_PHASE(bA, bB) \
    do { \
        _Pragma("unroll") \
        for (int ks = 0; ks < 4; ks++) { \
            uint32_t af[4][4]; \
            _Pragma("unroll") \
            for (int mt = 0; mt < 4; mt++) { \
                uint32_t aoff = ((uint32_t)(wm + mt * 16) * FST + lrow + ks * 8) * 4u; \
                LDSM_X4(af[mt], (bA) + aoff); \
            } \
            uint32_t bf[2][4]; \
            _Pragma("unroll") \
            for (int nb = 0; nb < 2; nb++) { \
                uint32_t boff = ((uint32_t)(wn + nb * 16) * FST + lrow + ks * 8) * 4u; \
                LDSM_X4(bf[nb], (bB) + boff); \
            } \
            _Pragma("unroll") \
            for (int mt = 0; mt < 4; mt++) \
                _Pragma("unroll") \
                for (int nb = 0; nb < 2; nb++) { \
                    MMA_TF32(acc[mt][nb * 2 + 0], af[mt], bf[nb][0], bf[nb][2]); \
                    MMA_TF32(acc[mt][nb * 2 + 1], af[mt], bf[nb][1], bf[nb][3]); \
                } \
        } \
    } while (0)

// ---------------- G1: E = tf32(exp((C*w3)^T Q + c1 + q2)), fused bias + sum partials ----------------
__global__ __launch_bounds__(256) void g1(
    const float* __restrict__ C, const float* __restrict__ Q,
    const float* __restrict__ w,
    const float* __restrict__ cmask, const float* __restrict__ qmask,
    float* __restrict__ E, float* __restrict__ rp, float* __restrict__ cp)
{
    __shared__ __align__(16) float sA[128 * FST];
    __shared__ __align__(16) float sB[128 * FST];
    __shared__ float sbias[4][128];
    __shared__ float srow[128][4];
    __shared__ float scol[128][2];

    const int zb = blockIdx.z;
    const int m0 = blockIdx.y << 7;      // l tile
    const int n0 = blockIdx.x << 7;      // m' tile
    const float* Cb = C + (size_t)zb * D_ * LC;
    const float* Qb = Q + (size_t)zb * D_ * LQ;
    const float* w1 = w, *w2 = w + D_, *w3 = w + 2 * D_;

    const int tid = threadIdx.x, wid = tid >> 5, lane = tid & 31;
    const int wm = (wid >> 2) * 64, wn = (wid & 3) * 32;

    float acc[4][4][4];
#pragma unroll
    for (int i = 0; i < 4; i++)
#pragma unroll
        for (int j = 0; j < 4; j++)
#pragma unroll
            for (int e = 0; e < 4; e++) acc[i][j][e] = 0.f;

    float4 ra[4], rb[4];
    float c1p = 0.f, q2p = 0.f;

    auto ldg = [&](int kk) {
#pragma unroll
        for (int i = 0; i < 4; i++) {
            int v = i * 256 + tid;
            int mn = v & 127, krb = v >> 7;
            int k0i = kk + krb * 4;
            {
                const float* p = Cb + (size_t)k0i * LC + m0 + mn;
                float4 x;
                x.x = p[0]; x.y = p[LC]; x.z = p[2 * LC]; x.w = p[3 * LC];
                c1p += x.x * __ldg(w1 + k0i)     + x.y * __ldg(w1 + k0i + 1)
                     + x.z * __ldg(w1 + k0i + 2) + x.w * __ldg(w1 + k0i + 3);
                x.x *= __ldg(w3 + k0i);     x.y *= __ldg(w3 + k0i + 1);
                x.z *= __ldg(w3 + k0i + 2); x.w *= __ldg(w3 + k0i + 3);
                ra[i] = x;
            }
            {
                const float* p = Qb + (size_t)k0i * LQ + n0 + mn;
                float4 x;
                x.x = p[0]; x.y = p[LQ]; x.z = p[2 * LQ]; x.w = p[3 * LQ];
                q2p += x.x * __ldg(w2 + k0i)     + x.y * __ldg(w2 + k0i + 1)
                     + x.z * __ldg(w2 + k0i + 2) + x.w * __ldg(w2 + k0i + 3);
                rb[i] = x;
            }
        }
    };
    auto sts = [&]() {
#pragma unroll
        for (int i = 0; i < 4; i++) {
            int v = i * 256 + tid;
            int mn = v & 127, krb = v >> 7;
            int off = mn * FST + krb * 4;
            *reinterpret_cast<float4*>(sA + off) = cvt_sel<true>(ra[i]);
            *reinterpret_cast<float4*>(sB + off) = cvt_sel<true>(rb[i]);
        }
    };

    const uint32_t bA = smem_u32(sA), bB = smem_u32(sB);
    const uint32_t lrow = (uint32_t)(lane & 15) * FST + ((lane >> 4) << 2);

    const int nch = D_ >> 5;   // 4
    ldg(0);
    for (int ch = 0; ch < nch; ch++) {
        sts();
        __syncthreads();
        if (ch + 1 < nch) ldg((ch + 1) << 5);
        MMA_PHASE(bA, bB);
        __syncthreads();
    }

    sbias[tid >> 7][tid & 127]       = c1p;
    sbias[2 + (tid >> 7)][tid & 127] = q2p;
    __syncthreads();

    float* Eb = E + (size_t)zb * LC * LQ;
    float cs[8];
#pragma unroll
    for (int j = 0; j < 8; j++) cs[j] = 0.f;

#pragma unroll
    for (int mt = 0; mt < 4; mt++) {
        int rl0 = wm + mt * 16 + (lane >> 2);
        int rl1 = rl0 + 8;
        int r0 = m0 + rl0, r1 = m0 + rl1;
        float br0 = sbias[0][rl0] + sbias[1][rl0];
        float br1 = sbias[0][rl1] + sbias[1][rl1];
        float cm0 = cmask[zb * LC + r0], cm1 = cmask[zb * LC + r1];
        float rs0 = 0.f, rs1 = 0.f;
#pragma unroll
        for (int nt = 0; nt < 4; nt++) {
            int cl = wn + nt * 8 + (lane & 3) * 2;
            int col = n0 + cl;
            float bc0 = sbias[2][cl] + sbias[3][cl];
            float bc1 = sbias[2][cl + 1] + sbias[3][cl + 1];
            float2 v0, v1;
            v0.x = tf32r(__expf(acc[mt][nt][0] + br0 + bc0));
            v0.y = tf32r(__expf(acc[mt][nt][1] + br0 + bc1));
            v1.x = tf32r(__expf(acc[mt][nt][2] + br1 + bc0));
            v1.y = tf32r(__expf(acc[mt][nt][3] + br1 + bc1));
            *reinterpret_cast<float2*>(Eb + (size_t)r0 * LQ + col) = v0;
            *reinterpret_cast<float2*>(Eb + (size_t)r1 * LQ + col) = v1;
            float qa = qmask[zb * LQ + col], qb = qmask[zb * LQ + col + 1];
            rs0 += v0.x * qa + v0.y * qb;
            rs1 += v1.x * qa + v1.y * qb;
            cs[nt * 2 + 0] += v0.x * cm0 + v1.x * cm1;
            cs[nt * 2 + 1] += v0.y * cm0 + v1.y * cm1;
        }
        rs0 += __shfl_xor_sync(0xffffffffu, rs0, 1);
        rs0 += __shfl_xor_sync(0xffffffffu, rs0, 2);
        rs1 += __shfl_xor_sync(0xffffffffu, rs1, 1);
        rs1 += __shfl_xor_sync(0xffffffffu, rs1, 2);
        if ((lane & 3) == 0) {
            srow[rl0][wid & 3] = rs0;
            srow[rl1][wid & 3] = rs1;
        }
    }
#pragma unroll
    for (int j = 0; j < 8; j++) {
        cs[j] += __shfl_xor_sync(0xffffffffu, cs[j], 4);
        cs[j] += __shfl_xor_sync(0xffffffffu, cs[j], 8);
        cs[j] += __shfl_xor_sync(0xffffffffu, cs[j], 16);
    }
    if (lane < 4) {
#pragma unroll
        for (int nt = 0; nt < 4; nt++)
#pragma unroll
            for (int e = 0; e < 2; e++) {
                int cl = wn + nt * 8 + lane * 2 + e;
                scol[cl][wid >> 2] = cs[nt * 2 + e];
            }
    }
    __syncthreads();
    if (tid < 128) {
        float r = srow[tid][0] + srow[tid][1] + srow[tid][2] + srow[tid][3];
        rp[((size_t)zb * 2 + blockIdx.x) * LC + m0 + tid] = r;
        float c = scol[tid][0] + scol[tid][1];
        cp[((size_t)zb * 8 + blockIdx.y) * LQ + n0 + tid] = c;
    }
}

// ---------------- G3 (split-K 2): Tt[d][m'] partial = (sum_{l in split} E(l,m')*cm(l)*C(d,l)) * qcinv(m') ----------------
__global__ __launch_bounds__(256) void g3(
    const float* __restrict__ E, const float* __restrict__ C,
    const float* __restrict__ cmask, const float* __restrict__ qmask,
    const float* __restrict__ cp, float* __restrict__ Tt)
{
    __shared__ __align__(16) float pool[2 * 128 * FST];   // sA | sB, reused as transpose buffer
    float* sA = pool;
    float* sB = pool + 128 * FST;
    __shared__ float sqc[128];

    const int zb = blockIdx.z >> 1;
    const int sp = blockIdx.z & 1;
    const int k0 = sp * (LC / 2);
    const int m0 = blockIdx.y << 7;      // m' tile
    const float* Eb = E + (size_t)zb * LC * LQ;
    const float* Cb = C + (size_t)zb * D_ * LC;
    const float* cm = cmask + zb * LC;

    const int tid = threadIdx.x, wid = tid >> 5, lane = tid & 31;
    const int wm = (wid >> 2) * 64, wn = (wid & 3) * 32;

    // prologue: qcinv for this m' tile
    if (tid < 128) {
        int m = m0 + tid;
        float c = 0.f;
#pragma unroll
        for (int y = 0; y < 8; y++) c += cp[((size_t)zb * 8 + y) * LQ + m];
        sqc[tid] = qmask[zb * LQ + m] / c;
    }

    float acc[4][4][4];
#pragma unroll
    for (int i = 0; i < 4; i++)
#pragma unroll
        for (int j = 0; j < 4; j++)
#pragma unroll
            for (int e = 0; e < 4; e++) acc[i][j][e] = 0.f;

    float4 ra[4], rb[4];

    auto ldg = [&](int kk) {
#pragma unroll
        for (int i = 0; i < 4; i++) {
            int v = i * 256 + tid;
            {   // A = E^T (K-slow, pre-rounded)
                int mn = v & 127, krb = v >> 7;
                const float* p = Eb + (size_t)(kk + krb * 4) * LQ + m0 + mn;
                float4 x;
                x.x = p[0]; x.y = p[LQ]; x.z = p[2 * LQ]; x.w = p[3 * LQ];
                ra[i] = x;
            }
            {   // B = C (K-fast) * cmask[k]
                int row = v >> 3, c4 = v & 7;
                float4 x = *reinterpret_cast<const float4*>(Cb + (size_t)row * LC + kk + c4 * 4);
                float4 s = *reinterpret_cast<const float4*>(cm + kk + c4 * 4);
                x.x *= s.x; x.y *= s.y; x.z *= s.z; x.w *= s.w;
                rb[i] = x;
            }
        }
    };
    auto sts = [&]() {
#pragma unroll
        for (int i = 0; i < 4; i++) {
            int v = i * 256 + tid;
            {
                int mn = v & 127, krb = v >> 7;
                *reinterpret_cast<float4*>(sA + mn * FST + krb * 4) = ra[i];
            }
            {
                int row = v >> 3, c4 = v & 7;
                *reinterpret_cast<float4*>(sB + row * FST + c4 * 4) = cvt_sel<true>(rb[i]);
            }
        }
    };

    const uint32_t bA = smem_u32(sA), bB = smem_u32(sB);
    const uint32_t lrow = (uint32_t)(lane & 15) * FST + ((lane >> 4) << 2);

    const int nch = (LC / 2) >> 5;   // 16
    ldg(k0);
    for (int ch = 0; ch < nch; ch++) {
        sts();
        __syncthreads();
        if (ch + 1 < nch) ldg(k0 + ((ch + 1) << 5));
        MMA_PHASE(bA, bB);
        __syncthreads();
    }

    // epilogue: scale by qcinv[m'], transpose via smem pool, write Tt[d][m'] coalesced
    float* Ttb = Tt + ((size_t)zb * 2 + sp) * D_ * LQ;
    float* st = pool;   // 64 x 132 floats = 8448 <= 9216
#pragma unroll
    for (int h = 0; h < 2; h++) {
        __syncthreads();
#pragma unroll
        for (int mt = 0; mt < 4; mt++) {
            int r0l = wm + mt * 16 + (lane >> 2);
            float s0 = sqc[r0l], s1 = sqc[r0l + 8];
#pragma unroll
            for (int nt = 0; nt < 4; nt++) {
                int cl = wn + nt * 8 + (lane & 3) * 2;
                if ((cl >> 6) == h) {
                    int dl = cl & 63;
                    st[dl * 132 + r0l]           = acc[mt][nt][0] * s0;
                    st[(dl + 1) * 132 + r0l]     = acc[mt][nt][1] * s0;
                    st[dl * 132 + r0l + 8]       = acc[mt][nt][2] * s1;
                    st[(dl + 1) * 132 + r0l + 8] = acc[mt][nt][3] * s1;
                }
            }
        }
        __syncthreads();
#pragma unroll
        for (int i = 0; i < 8; i++) {
            int v = i * 256 + tid;           // 2048 float4 slots: 64 d rows x 32 m'-float4
            int dr = v >> 5, m4 = v & 31;
            float4 x = *reinterpret_cast<const float4*>(st + dr * 132 + m4 * 4);
            *reinterpret_cast<float4*>(Ttb + (size_t)(h * 64 + dr) * LQ + m0 + m4 * 4) = x;
        }
    }
}

// ---------------- fused G2+G4: A = [Q*qm ; Tt0+Tt1], B = E tile ----------------
__global__ __launch_bounds__(256) void g24(
    const float* __restrict__ Q, const float* __restrict__ Tt,
    const float* __restrict__ E, const float* __restrict__ C,
    const float* __restrict__ qmask, const float* __restrict__ rp,
    float* __restrict__ out)
{
    __shared__ __align__(16) float sA[256 * FST];
    __shared__ __align__(16) float sB[64 * FST];
    __shared__ float srv[64];    // rinv for this CTA's l-tile

    const int zb = blockIdx.z;
    const int n0 = blockIdx.x * 64;
    const float* Qb = Q + (size_t)zb * D_ * LQ;
    const float* Tb = Tt + (size_t)zb * 2 * D_ * LQ;
    const float* Eb = E + (size_t)zb * LC * LQ;
    const float* qm = qmask + zb * LQ;

    const int tid = threadIdx.x, wid = tid >> 5, lane = tid & 31;
    const int wm = (wid >> 1) * 64, wn = (wid & 1) * 32;

    if (tid < 64) {
        float s = rp[((size_t)zb * 2 + 0) * LC + n0 + tid]
                + rp[((size_t)zb * 2 + 1) * LC + n0 + tid];
        srv[tid] = 1.f / s;
    }

    float acc[4][4][4];
#pragma unroll
    for (int i = 0; i < 4; i++)
#pragma unroll
        for (int j = 0; j < 4; j++)
#pragma unroll
            for (int e = 0; e < 4; e++) acc[i][j][e] = 0.f;

    float4 ra[8], rb[2];

    auto ldg = [&](int kk) {
#pragma unroll
        for (int i = 0; i < 8; i++) {
            int v = i * 256 + tid;
            int row = v >> 3, c4 = v & 7;
            if (i < 4) {        // Q half (rows 0..127), * qmask[k]
                float4 x = *reinterpret_cast<const float4*>(Qb + (size_t)row * LQ + kk + c4 * 4);
                float4 s = *reinterpret_cast<const float4*>(qm + kk + c4 * 4);
                x.x *= s.x; x.y *= s.y; x.z *= s.z; x.w *= s.w;
                ra[i] = x;
            } else {            // Tt half (rows 128..255): sum of 2 split partials, K-fast
                const float* p0 = Tb + (size_t)(row - 128) * LQ + kk + c4 * 4;
                float4 a = *reinterpret_cast<const float4*>(p0);
                float4 b = *reinterpret_cast<const float4*>(p0 + (size_t)D_ * LQ);
                float4 x;
                x.x = a.x + b.x; x.y = a.y + b.y; x.z = a.z + b.z; x.w = a.w + b.w;
                ra[i] = x;
            }
        }
#pragma unroll
        for (int i = 0; i < 2; i++) {   // E tile, 64 rows (l), pre-rounded
            int v = i * 256 + tid;
            int row = v >> 3, c4 = v & 7;
            rb[i] = *reinterpret_cast<const float4*>(Eb + (size_t)(n0 + row) * LQ + kk + c4 * 4);
        }
    };
    auto sts = [&]() {
#pragma unroll
        for (int i = 0; i < 8; i++) {
            int v = i * 256 + tid;
            int row = v >> 3, c4 = v & 7;
            *reinterpret_cast<float4*>(sA + row * FST + c4 * 4) = cvt_sel<true>(ra[i]);
        }
#pragma unroll
        for (int i = 0; i < 2; i++) {
            int v = i * 256 + tid;
            int row = v >> 3, c4 = v & 7;
            *reinterpret_cast<float4*>(sB + row * FST + c4 * 4) = rb[i];
        }
    };

    const uint32_t bA = smem_u32(sA), bB = smem_u32(sB);
    const uint32_t lrow = (uint32_t)(lane & 15) * FST + ((lane >> 4) << 2);

    const int nch = LQ >> 5;   // 8
    ldg(0);
    for (int ch = 0; ch < nch; ch++) {
        sts();
        __syncthreads();
        if (ch + 1 < nch) ldg((ch + 1) << 5);
        MMA_PHASE(bA, bB);
        __syncthreads();
    }

    // epilogue: rows < 128 => At (channels 0,1,2); rows >= 128 => Bv (channel 3)
    const float* Cb = C + (size_t)zb * D_ * LC;
    float* O = out + (size_t)zb * 4 * D_ * LC;
#pragma unroll
    for (int mt = 0; mt < 4; mt++) {
        int r0 = wm + mt * 16 + (lane >> 2);
        int r1 = r0 + 8;
#pragma unroll
        for (int nt = 0; nt < 4; nt++) {
            int cl = wn + nt * 8 + (lane & 3) * 2;
            int col = n0 + cl;
            float c0 = srv[cl], c1v = srv[cl + 1];
            float2 v0, v1;
            v0.x = acc[mt][nt][0] * c0; v0.y = acc[mt][nt][1] * c1v;
            v1.x = acc[mt][nt][2] * c0; v1.y = acc[mt][nt][3] * c1v;
            if (wm < 128) {
                int d0 = r0, d1 = r1;
                float2 cc0 = *reinterpret_cast<const float2*>(Cb + (size_t)d0 * LC + col);
                float2 cc1 = *reinterpret_cast<const float2*>(Cb + (size_t)d1 * LC + col);
                *reinterpret_cast<float2*>(O + (size_t)d0 * LC + col) = cc0;
                *reinterpret_cast<float2*>(O + (size_t)d1 * LC + col) = cc1;
                *reinterpret_cast<float2*>(O + (size_t)(D_ + d0) * LC + col) = v0;
                *reinterpret_cast<float2*>(O + (size_t)(D_ + d1) * LC + col) = v1;
                float2 m0v, m1v;
                m0v.x = cc0.x * v0.x; m0v.y = cc0.y * v0.y;
                m1v.x = cc1.x * v1.x; m1v.y = cc1.y * v1.y;
                *reinterpret_cast<float2*>(O + (size_t)(2 * D_ + d0) * LC + col) = m0v;
                *reinterpret_cast<float2*>(O + (size_t)(2 * D_ + d1) * LC + col) = m1v;
            } else {
                int d0 = r0 - 128, d1 = r1 - 128;
                float2 cc0 = *reinterpret_cast<const float2*>(Cb + (size_t)d0 * LC + col);
                float2 cc1 = *reinterpret_cast<const float2*>(Cb + (size_t)d1 * LC + col);
                float2 b0v, b1v;
                b0v.x = cc0.x * v0.x; b0v.y = cc0.y * v0.y;
                b1v.x = cc1.x * v1.x; b1v.y = cc1.y * v1.y;
                *reinterpret_cast<float2*>(O + (size_t)(3 * D_ + d0) * LC + col) = b0v;
                *reinterpret_cast<float2*>(O + (size_t)(3 * D_ + d1) * LC + col) = b1v;
            }
        }
    }
}

// ---------------- launch ----------------
extern "C" void kernel_launch(void* const* d_in, const int* in_sizes, int n_in,
                              void* d_out, int out_size) {
    const float* C     = (const float*)d_in[0];
    const float* Q     = (const float*)d_in[1];
    const float* cmask = (const float*)d_in[2];
    const float* qmask = (const float*)d_in[3];
    const float* w     = (const float*)d_in[4];
    float* out = (float*)d_out;

    float *pE, *pTt, *prp, *pcp;
    cudaGetSymbolAddress((void**)&pE,  g_E);
    cudaGetSymbolAddress((void**)&pTt, g_Tt);
    cudaGetSymbolAddress((void**)&prp, g_rp);
    cudaGetSymbolAddress((void**)&pcp, g_cp);

    // 1: G1 (fused bias + E + sum partials)
    g1<<<dim3(2, 8, B_), 256>>>(C, Q, w, cmask, qmask, pE, prp, pcp);

    // 2: G3 split-K 2, writes transposed pre-scaled Tt partials
    g3<<<dim3(1, 2, B_ * 2), 256>>>(pE, C, cmask, qmask, pcp, pTt);

    // 3: fused G2+G4 + output assembly
    g24<<<dim3(LC / 64, 1, B_), 256>>>(Q, pTt, pE, C, qmask, prp, out);
}

// round 17
// speedup vs baseline: 1.0731x; 1.0731x over previous
#include <cuda_runtime.h>
#include <cuda_bf16.h>
#include <cstdint>

#define B_  64
#define D_  128
#define LC  1024
#define LQ  256
#define FST 36       // fp32 smem row stride (144B: conflict-free STS.128 + ldmatrix)

// ---------------- scratch (static device arrays) ----------------
static __device__ float g_E [(size_t)B_*LC*LQ];     // exp(S + biases), tf32-rounded
static __device__ float g_Tt[(size_t)B_*2*D_*LQ];   // Tt partials: [b][split][d][m'], pre-scaled by qcinv
static __device__ float g_rp[(size_t)B_*2*LC];      // rowsum partials (per x-tile)
static __device__ float g_cp[(size_t)B_*8*LQ];      // colsum partials (per y-tile)
static __device__ float g_rinv[B_*LC];
static __device__ float g_qcinv[B_*LQ];

// ---------------- helpers ----------------
__device__ __forceinline__ uint32_t smem_u32(const void* p) {
    uint32_t a;
    asm("{ .reg .u64 t; cvta.to.shared.u64 t, %1; cvt.u32.u64 %0, t; }" : "=r"(a) : "l"(p));
    return a;
}

__device__ __forceinline__ float tf32r(float x) {
    uint32_t o; asm("cvt.rna.tf32.f32 %0, %1;" : "=r"(o) : "f"(x));
    return __uint_as_float(o);
}

#define LDSM_X4(r, a) \
    asm volatile("ldmatrix.sync.aligned.m8n8.x4.shared.b16 {%0,%1,%2,%3}, [%4];" \
        : "=r"((r)[0]), "=r"((r)[1]), "=r"((r)[2]), "=r"((r)[3]) : "r"(a))

#define MMA_TF32(c, a, b0, b1) \
    asm volatile("mma.sync.aligned.m16n8k8.row.col.f32.tf32.tf32.f32 " \
        "{%0,%1,%2,%3}, {%4,%5,%6,%7}, {%8,%9}, {%0,%1,%2,%3};" \
        : "+f"((c)[0]), "+f"((c)[1]), "+f"((c)[2]), "+f"((c)[3]) \
        : "r"((a)[0]), "r"((a)[1]), "r"((a)[2]), "r"((a)[3]), "r"(b0), "r"(b1))

template<bool CV>
__device__ __forceinline__ float4 cvt_sel(const float4& x) {
    if constexpr (!CV) return x;
    float4 t;
    t.x = tf32r(x.x); t.y = tf32r(x.y); t.z = tf32r(x.z); t.w = tf32r(x.w);
    return t;
}

// ---------------- shared MMA phase (A 128-row, B 128-col tiles, warp 64x32) ----------------
#define MMA_PHASE(bA, bB) \
    do { \
        _Pragma("unroll") \
        for (int ks = 0; ks < 4; ks++) { \
            uint32_t af[4][4]; \
            _Pragma("unroll") \
            for (int mt = 0; mt < 4; mt++) { \
                uint32_t aoff = ((uint32_t)(wm + mt * 16) * FST + lrow + ks * 8) * 4u; \
                LDSM_X4(af[mt], (bA) + aoff); \
            } \
            uint32_t bf[2][4]; \
            _Pragma("unroll") \
            for (int nb = 0; nb < 2; nb++) { \
                uint32_t boff = ((uint32_t)(wn + nb * 16) * FST + lrow + ks * 8) * 4u; \
                LDSM_X4(bf[nb], (bB) + boff); \
            } \
            _Pragma("unroll") \
            for (int mt = 0; mt < 4; mt++) \
                _Pragma("unroll") \
                for (int nb = 0; nb < 2; nb++) { \
                    MMA_TF32(acc[mt][nb * 2 + 0], af[mt], bf[nb][0], bf[nb][2]); \
                    MMA_TF32(acc[mt][nb * 2 + 1], af[mt], bf[nb][1], bf[nb][3]); \
                } \
        } \
    } while (0)

// ---------------- G1: E = tf32(exp((C*w3)^T Q + c1 + q2)), fused bias + sum partials ----------------
__global__ __launch_bounds__(256) void g1(
    const float* __restrict__ C, const float* __restrict__ Q,
    const float* __restrict__ w,
    const float* __restrict__ cmask, const float* __restrict__ qmask,
    float* __restrict__ E, float* __restrict__ rp, float* __restrict__ cp)
{
    __shared__ __align__(16) float sA[128 * FST];
    __shared__ __align__(16) float sB[128 * FST];
    __shared__ float sbias[4][128];
    __shared__ float srow[128][4];
    __shared__ float scol[128][2];

    const int zb = blockIdx.z;
    const int m0 = blockIdx.y << 7;      // l tile
    const int n0 = blockIdx.x << 7;      // m' tile
    const float* Cb = C + (size_t)zb * D_ * LC;
    const float* Qb = Q + (size_t)zb * D_ * LQ;
    const float* w1 = w, *w2 = w + D_, *w3 = w + 2 * D_;

    const int tid = threadIdx.x, wid = tid >> 5, lane = tid & 31;
    const int wm = (wid >> 2) * 64, wn = (wid & 3) * 32;

    float acc[4][4][4];
#pragma unroll
    for (int i = 0; i < 4; i++)
#pragma unroll
        for (int j = 0; j < 4; j++)
#pragma unroll
            for (int e = 0; e < 4; e++) acc[i][j][e] = 0.f;

    float4 ra[4], rb[4];
    float c1p = 0.f, q2p = 0.f;

    auto ldg = [&](int kk) {
#pragma unroll
        for (int i = 0; i < 4; i++) {
            int v = i * 256 + tid;
            int mn = v & 127, krb = v >> 7;
            int k0i = kk + krb * 4;
            {
                const float* p = Cb + (size_t)k0i * LC + m0 + mn;
                float4 x;
                x.x = p[0]; x.y = p[LC]; x.z = p[2 * LC]; x.w = p[3 * LC];
                c1p += x.x * __ldg(w1 + k0i)     + x.y * __ldg(w1 + k0i + 1)
                     + x.z * __ldg(w1 + k0i + 2) + x.w * __ldg(w1 + k0i + 3);
                x.x *= __ldg(w3 + k0i);     x.y *= __ldg(w3 + k0i + 1);
                x.z *= __ldg(w3 + k0i + 2); x.w *= __ldg(w3 + k0i + 3);
                ra[i] = x;
            }
            {
                const float* p = Qb + (size_t)k0i * LQ + n0 + mn;
                float4 x;
                x.x = p[0]; x.y = p[LQ]; x.z = p[2 * LQ]; x.w = p[3 * LQ];
                q2p += x.x * __ldg(w2 + k0i)     + x.y * __ldg(w2 + k0i + 1)
                     + x.z * __ldg(w2 + k0i + 2) + x.w * __ldg(w2 + k0i + 3);
                rb[i] = x;
            }
        }
    };
    auto sts = [&]() {
#pragma unroll
        for (int i = 0; i < 4; i++) {
            int v = i * 256 + tid;
            int mn = v & 127, krb = v >> 7;
            int off = mn * FST + krb * 4;
            *reinterpret_cast<float4*>(sA + off) = cvt_sel<true>(ra[i]);
            *reinterpret_cast<float4*>(sB + off) = cvt_sel<true>(rb[i]);
        }
    };

    const uint32_t bA = smem_u32(sA), bB = smem_u32(sB);
    const uint32_t lrow = (uint32_t)(lane & 15) * FST + ((lane >> 4) << 2);

    const int nch = D_ >> 5;   // 4
    ldg(0);
    for (int ch = 0; ch < nch; ch++) {
        sts();
        __syncthreads();
        if (ch + 1 < nch) ldg((ch + 1) << 5);
        MMA_PHASE(bA, bB);
        __syncthreads();
    }

    sbias[tid >> 7][tid & 127]       = c1p;
    sbias[2 + (tid >> 7)][tid & 127] = q2p;
    __syncthreads();

    float* Eb = E + (size_t)zb * LC * LQ;
    float cs[8];
#pragma unroll
    for (int j = 0; j < 8; j++) cs[j] = 0.f;

#pragma unroll
    for (int mt = 0; mt < 4; mt++) {
        int rl0 = wm + mt * 16 + (lane >> 2);
        int rl1 = rl0 + 8;
        int r0 = m0 + rl0, r1 = m0 + rl1;
        float br0 = sbias[0][rl0] + sbias[1][rl0];
        float br1 = sbias[0][rl1] + sbias[1][rl1];
        float cm0 = cmask[zb * LC + r0], cm1 = cmask[zb * LC + r1];
        float rs0 = 0.f, rs1 = 0.f;
#pragma unroll
        for (int nt = 0; nt < 4; nt++) {
            int cl = wn + nt * 8 + (lane & 3) * 2;
            int col = n0 + cl;
            float bc0 = sbias[2][cl] + sbias[3][cl];
            float bc1 = sbias[2][cl + 1] + sbias[3][cl + 1];
            float2 v0, v1;
            v0.x = tf32r(__expf(acc[mt][nt][0] + br0 + bc0));
            v0.y = tf32r(__expf(acc[mt][nt][1] + br0 + bc1));
            v1.x = tf32r(__expf(acc[mt][nt][2] + br1 + bc0));
            v1.y = tf32r(__expf(acc[mt][nt][3] + br1 + bc1));
            *reinterpret_cast<float2*>(Eb + (size_t)r0 * LQ + col) = v0;
            *reinterpret_cast<float2*>(Eb + (size_t)r1 * LQ + col) = v1;
            float qa = qmask[zb * LQ + col], qb = qmask[zb * LQ + col + 1];
            rs0 += v0.x * qa + v0.y * qb;
            rs1 += v1.x * qa + v1.y * qb;
            cs[nt * 2 + 0] += v0.x * cm0 + v1.x * cm1;
            cs[nt * 2 + 1] += v0.y * cm0 + v1.y * cm1;
        }
        rs0 += __shfl_xor_sync(0xffffffffu, rs0, 1);
        rs0 += __shfl_xor_sync(0xffffffffu, rs0, 2);
        rs1 += __shfl_xor_sync(0xffffffffu, rs1, 1);
        rs1 += __shfl_xor_sync(0xffffffffu, rs1, 2);
        if ((lane & 3) == 0) {
            srow[rl0][wid & 3] = rs0;
            srow[rl1][wid & 3] = rs1;
        }
    }
#pragma unroll
    for (int j = 0; j < 8; j++) {
        cs[j] += __shfl_xor_sync(0xffffffffu, cs[j], 4);
        cs[j] += __shfl_xor_sync(0xffffffffu, cs[j], 8);
        cs[j] += __shfl_xor_sync(0xffffffffu, cs[j], 16);
    }
    if (lane < 4) {
#pragma unroll
        for (int nt = 0; nt < 4; nt++)
#pragma unroll
            for (int e = 0; e < 2; e++) {
                int cl = wn + nt * 8 + lane * 2 + e;
                scol[cl][wid >> 2] = cs[nt * 2 + e];
            }
    }
    __syncthreads();
    if (tid < 128) {
        float r = srow[tid][0] + srow[tid][1] + srow[tid][2] + srow[tid][3];
        rp[((size_t)zb * 2 + blockIdx.x) * LC + m0 + tid] = r;
        float c = scol[tid][0] + scol[tid][1];
        cp[((size_t)zb * 8 + blockIdx.y) * LQ + n0 + tid] = c;
    }
}

// ---------------- finish: rinv, qcinv from partials ----------------
__global__ void k_finish(const float* __restrict__ qmask) {
    int b = blockIdx.x;
    for (int l = threadIdx.x; l < LC; l += 256) {
        float s = g_rp[((size_t)b * 2 + 0) * LC + l] + g_rp[((size_t)b * 2 + 1) * LC + l];
        g_rinv[b * LC + l] = 1.f / s;
    }
    int m = threadIdx.x;
    float c = 0.f;
#pragma unroll
    for (int y = 0; y < 8; y++) c += g_cp[((size_t)b * 8 + y) * LQ + m];
    g_qcinv[b * LQ + m] = qmask[b * LQ + m] / c;
}

// ---------------- G3 (split-K 2): Tt[d][m'] partial = (sum_{l in split} E*cm*C) * qcinv(m') ----------------
__global__ __launch_bounds__(256) void g3(
    const float* __restrict__ E, const float* __restrict__ C,
    const float* __restrict__ cmask, const float* __restrict__ qcinv,
    float* __restrict__ Tt)
{
    __shared__ __align__(16) float pool[2 * 128 * FST];
    float* sA = pool;
    float* sB = pool + 128 * FST;
    __shared__ float sqc[128];

    const int zb = blockIdx.z >> 1;
    const int sp = blockIdx.z & 1;
    const int k0 = sp * (LC / 2);
    const int m0 = blockIdx.y << 7;      // m' tile
    const float* Eb = E + (size_t)zb * LC * LQ;
    const float* Cb = C + (size_t)zb * D_ * LC;
    const float* cm = cmask + zb * LC;

    const int tid = threadIdx.x, wid = tid >> 5, lane = tid & 31;
    const int wm = (wid >> 2) * 64, wn = (wid & 3) * 32;

    if (tid < 128) sqc[tid] = qcinv[zb * LQ + m0 + tid];

    float acc[4][4][4];
#pragma unroll
    for (int i = 0; i < 4; i++)
#pragma unroll
        for (int j = 0; j < 4; j++)
#pragma unroll
            for (int e = 0; e < 4; e++) acc[i][j][e] = 0.f;

    float4 ra[4], rb[4];

    auto ldg = [&](int kk) {
#pragma unroll
        for (int i = 0; i < 4; i++) {
            int v = i * 256 + tid;
            {
                int mn = v & 127, krb = v >> 7;
                const float* p = Eb + (size_t)(kk + krb * 4) * LQ + m0 + mn;
                float4 x;
                x.x = p[0]; x.y = p[LQ]; x.z = p[2 * LQ]; x.w = p[3 * LQ];
                ra[i] = x;
            }
            {
                int row = v >> 3, c4 = v & 7;
                float4 x = *reinterpret_cast<const float4*>(Cb + (size_t)row * LC + kk + c4 * 4);
                float4 s = *reinterpret_cast<const float4*>(cm + kk + c4 * 4);
                x.x *= s.x; x.y *= s.y; x.z *= s.z; x.w *= s.w;
                rb[i] = x;
            }
        }
    };
    auto sts = [&]() {
#pragma unroll
        for (int i = 0; i < 4; i++) {
            int v = i * 256 + tid;
            {
                int mn = v & 127, krb = v >> 7;
                *reinterpret_cast<float4*>(sA + mn * FST + krb * 4) = ra[i];
            }
            {
                int row = v >> 3, c4 = v & 7;
                *reinterpret_cast<float4*>(sB + row * FST + c4 * 4) = cvt_sel<true>(rb[i]);
            }
        }
    };

    const uint32_t bA = smem_u32(sA), bB = smem_u32(sB);
    const uint32_t lrow = (uint32_t)(lane & 15) * FST + ((lane >> 4) << 2);

    const int nch = (LC / 2) >> 5;   // 16
    ldg(k0);
    for (int ch = 0; ch < nch; ch++) {
        sts();
        __syncthreads();
        if (ch + 1 < nch) ldg(k0 + ((ch + 1) << 5));
        MMA_PHASE(bA, bB);
        __syncthreads();
    }

    // epilogue: scale by qcinv[m'], transpose via smem pool, write Tt[d][m'] coalesced
    float* Ttb = Tt + ((size_t)zb * 2 + sp) * D_ * LQ;
    float* st = pool;
#pragma unroll
    for (int h = 0; h < 2; h++) {
        __syncthreads();
#pragma unroll
        for (int mt = 0; mt < 4; mt++) {
            int r0l = wm + mt * 16 + (lane >> 2);
            float s0 = sqc[r0l], s1 = sqc[r0l + 8];
#pragma unroll
            for (int nt = 0; nt < 4; nt++) {
                int cl = wn + nt * 8 + (lane & 3) * 2;
                if ((cl >> 6) == h) {
                    int dl = cl & 63;
                    st[dl * 132 + r0l]           = acc[mt][nt][0] * s0;
                    st[(dl + 1) * 132 + r0l]     = acc[mt][nt][1] * s0;
                    st[dl * 132 + r0l + 8]       = acc[mt][nt][2] * s1;
                    st[(dl + 1) * 132 + r0l + 8] = acc[mt][nt][3] * s1;
                }
            }
        }
        __syncthreads();
#pragma unroll
        for (int i = 0; i < 8; i++) {
            int v = i * 256 + tid;
            int dr = v >> 5, m4 = v & 31;
            float4 x = *reinterpret_cast<const float4*>(st + dr * 132 + m4 * 4);
            *reinterpret_cast<float4*>(Ttb + (size_t)(h * 64 + dr) * LQ + m0 + m4 * 4) = x;
        }
    }
}

// ---------------- fused G2+G4, BN=128: A = [Q*qm ; Tt0+Tt1] (256 rows), B = E 128-row tile ----------------
__global__ __launch_bounds__(256) void g24(
    const float* __restrict__ Q, const float* __restrict__ Tt,
    const float* __restrict__ E, const float* __restrict__ C,
    const float* __restrict__ qmask, const float* __restrict__ rinv,
    float* __restrict__ out)
{
    extern __shared__ __align__(16) float smd[];
    float* sA = smd;                 // 256 * FST
    float* sB = smd + 256 * FST;     // 128 * FST
    __shared__ float srv[128];

    const int zb = blockIdx.z;
    const int n0 = blockIdx.x << 7;  // l tile of 128
    const float* Qb = Q + (size_t)zb * D_ * LQ;
    const float* Tb = Tt + (size_t)zb * 2 * D_ * LQ;
    const float* Eb = E + (size_t)zb * LC * LQ;
    const float* qm = qmask + zb * LQ;

    const int tid = threadIdx.x, wid = tid >> 5, lane = tid & 31;
    const int wm = (wid >> 1) * 64, wn = (wid & 1) * 64;

    if (tid < 128) srv[tid] = rinv[zb * LC + n0 + tid];

    float acc[4][8][4];
#pragma unroll
    for (int i = 0; i < 4; i++)
#pragma unroll
        for (int j = 0; j < 8; j++)
#pragma unroll
            for (int e = 0; e < 4; e++) acc[i][j][e] = 0.f;

    float4 ra[8], rb[4];

    auto ldg = [&](int kk) {
#pragma unroll
        for (int i = 0; i < 4; i++) {   // Q half (rows 0..127), * qmask[k]
            int v = i * 256 + tid;
            int row = v >> 3, c4 = v & 7;
            float4 x = *reinterpret_cast<const float4*>(Qb + (size_t)row * LQ + kk + c4 * 4);
            float4 s = *reinterpret_cast<const float4*>(qm + kk + c4 * 4);
            x.x *= s.x; x.y *= s.y; x.z *= s.z; x.w *= s.w;
            ra[i] = x;
        }
#pragma unroll
        for (int i = 0; i < 4; i++) {   // Tt half (rows 128..255): sum of 2 partials, K-fast
            int v = i * 256 + tid;
            int row = v >> 3, c4 = v & 7;
            const float* p0 = Tb + (size_t)row * LQ + kk + c4 * 4;
            float4 a = *reinterpret_cast<const float4*>(p0);
            float4 b = *reinterpret_cast<const float4*>(p0 + (size_t)D_ * LQ);
            float4 x;
            x.x = a.x + b.x; x.y = a.y + b.y; x.z = a.z + b.z; x.w = a.w + b.w;
            ra[4 + i] = x;
        }
#pragma unroll
        for (int i = 0; i < 4; i++) {   // E tile, 128 rows (l), pre-rounded
            int v = i * 256 + tid;
            int row = v >> 3, c4 = v & 7;
            rb[i] = *reinterpret_cast<const float4*>(Eb + (size_t)(n0 + row) * LQ + kk + c4 * 4);
        }
    };
    auto sts = [&]() {
#pragma unroll
        for (int i = 0; i < 4; i++) {
            int v = i * 256 + tid;
            int row = v >> 3, c4 = v & 7;
            *reinterpret_cast<float4*>(sA + row * FST + c4 * 4) = cvt_sel<true>(ra[i]);
        }
#pragma unroll
        for (int i = 0; i < 4; i++) {
            int v = i * 256 + tid;
            int row = v >> 3, c4 = v & 7;
            *reinterpret_cast<float4*>(sA + (128 + row) * FST + c4 * 4) = cvt_sel<true>(ra[4 + i]);
        }
#pragma unroll
        for (int i = 0; i < 4; i++) {
            int v = i * 256 + tid;
            int row = v >> 3, c4 = v & 7;
            *reinterpret_cast<float4*>(sB + row * FST + c4 * 4) = rb[i];
        }
    };

    const uint32_t bA = smem_u32(sA), bB = smem_u32(sB);
    const uint32_t lrow = (uint32_t)(lane & 15) * FST + ((lane >> 4) << 2);

    const int nch = LQ >> 5;   // 8
    ldg(0);
    for (int ch = 0; ch < nch; ch++) {
        sts();
        __syncthreads();
        if (ch + 1 < nch) ldg((ch + 1) << 5);
#pragma unroll
        for (int ks = 0; ks < 4; ks++) {
            uint32_t af[4][4];
#pragma unroll
            for (int mt = 0; mt < 4; mt++) {
                uint32_t aoff = ((uint32_t)(wm + mt * 16) * FST + lrow + ks * 8) * 4u;
                LDSM_X4(af[mt], bA + aoff);
            }
            uint32_t bf[4][4];
#pragma unroll
            for (int nb = 0; nb < 4; nb++) {
                uint32_t boff = ((uint32_t)(wn + nb * 16) * FST + lrow + ks * 8) * 4u;
                LDSM_X4(bf[nb], bB + boff);
            }
#pragma unroll
            for (int mt = 0; mt < 4; mt++)
#pragma unroll
                for (int nb = 0; nb < 4; nb++) {
                    MMA_TF32(acc[mt][nb * 2 + 0], af[mt], bf[nb][0], bf[nb][2]);
                    MMA_TF32(acc[mt][nb * 2 + 1], af[mt], bf[nb][1], bf[nb][3]);
                }
        }
        __syncthreads();
    }

    // epilogue: rows < 128 => At (channels 0,1,2); rows >= 128 => Bv (channel 3)
    const float* Cb = C + (size_t)zb * D_ * LC;
    float* O = out + (size_t)zb * 4 * D_ * LC;
#pragma unroll
    for (int mt = 0; mt < 4; mt++) {
        int r0 = wm + mt * 16 + (lane >> 2);
        int r1 = r0 + 8;
#pragma unroll
        for (int nt = 0; nt < 8; nt++) {
            int cl = wn + nt * 8 + (lane & 3) * 2;
            int col = n0 + cl;
            float c0 = srv[cl], c1v = srv[cl + 1];
            float2 v0, v1;
            v0.x = acc[mt][nt][0] * c0; v0.y = acc[mt][nt][1] * c1v;
            v1.x = acc[mt][nt][2] * c0; v1.y = acc[mt][nt][3] * c1v;
            if (wm < 128) {
                int d0 = r0, d1 = r1;
                float2 cc0 = *reinterpret_cast<const float2*>(Cb + (size_t)d0 * LC + col);
                float2 cc1 = *reinterpret_cast<const float2*>(Cb + (size_t)d1 * LC + col);
                *reinterpret_cast<float2*>(O + (size_t)d0 * LC + col) = cc0;
                *reinterpret_cast<float2*>(O + (size_t)d1 * LC + col) = cc1;
                *reinterpret_cast<float2*>(O + (size_t)(D_ + d0) * LC + col) = v0;
                *reinterpret_cast<float2*>(O + (size_t)(D_ + d1) * LC + col) = v1;
                float2 m0v, m1v;
                m0v.x = cc0.x * v0.x; m0v.y = cc0.y * v0.y;
                m1v.x = cc1.x * v1.x; m1v.y = cc1.y * v1.y;
                *reinterpret_cast<float2*>(O + (size_t)(2 * D_ + d0) * LC + col) = m0v;
                *reinterpret_cast<float2*>(O + (size_t)(2 * D_ + d1) * LC + col) = m1v;
            } else {
                int d0 = r0 - 128, d1 = r1 - 128;
                float2 cc0 = *reinterpret_cast<const float2*>(Cb + (size_t)d0 * LC + col);
                float2 cc1 = *reinterpret_cast<const float2*>(Cb + (size_t)d1 * LC + col);
                float2 b0v, b1v;
                b0v.x = cc0.x * v0.x; b0v.y = cc0.y * v0.y;
                b1v.x = cc1.x * v1.x; b1v.y = cc1.y * v1.y;
                *reinterpret_cast<float2*>(O + (size_t)(3 * D_ + d0) * LC + col) = b0v;
                *reinterpret_cast<float2*>(O + (size_t)(3 * D_ + d1) * LC + col) = b1v;
            }
        }
    }
}

// ---------------- launch ----------------
extern "C" void kernel_launch(void* const* d_in, const int* in_sizes, int n_in,
                              void* d_out, int out_size) {
    const float* C     = (const float*)d_in[0];
    const float* Q     = (const float*)d_in[1];
    const float* cmask = (const float*)d_in[2];
    const float* qmask = (const float*)d_in[3];
    const float* w     = (const float*)d_in[4];
    float* out = (float*)d_out;

    float *pE, *pTt, *prp, *pcp, *prv, *pqc;
    cudaGetSymbolAddress((void**)&pE,  g_E);
    cudaGetSymbolAddress((void**)&pTt, g_Tt);
    cudaGetSymbolAddress((void**)&prp, g_rp);
    cudaGetSymbolAddress((void**)&pcp, g_cp);
    cudaGetSymbolAddress((void**)&prv, g_rinv);
    cudaGetSymbolAddress((void**)&pqc, g_qcinv);

    const int G24_SMEM = (256 + 128) * FST * 4;   // 55296 B
    static int smem_set = 0;
    if (!smem_set) {
        cudaFuncSetAttribute(g24, cudaFuncAttributeMaxDynamicSharedMemorySize, G24_SMEM);
        smem_set = 1;
    }

    // 1: G1 (fused bias + E + sum partials)
    g1<<<dim3(2, 8, B_), 256>>>(C, Q, w, cmask, qmask, pE, prp, pcp);

    // 2: finish (rinv, qcinv)
    k_finish<<<B_, 256>>>(qmask);

    // 3: G3 split-K 2, transposed pre-scaled Tt partials
    g3<<<dim3(1, 2, B_ * 2), 256>>>(pE, C, cmask, pqc, pTt);

    // 4 (profiled): fused G2+G4 BN=128 + output assembly
    g24<<<dim3(LC / 128, 1, B_), 256, G24_SMEM>>>(Q, pTt, pE, C, qmask, prv, out);
}